// round 3
// baseline (speedup 1.0000x reference)
#include <cuda_runtime.h>
#include <math.h>

#define H 256
#define W 256
#define T 48
#define HWT (H*W*T)

// Output tile per block
#define OH 8
#define OW 8
#define OT 12
#define TT 4            // t-outputs per thread (register blocking)
#define NTHREADS 192    // 8 tx * 8 ty * 3 tg

// Halo'ed SMEM tile
#define HY 14           // OH + 6
#define HX 14           // OW + 6
#define HT 16           // OT + 4
#define ROWS (HY*HX)    // 196
#define PLANE (ROWS*HT) // 3136
#define NCH 18          // 9 guidance + 3 estimands + 3 variance + 3 images
#define SMEM_FLOATS (NCH*PLANE)   // 56448 -> 225792 bytes

__global__ __launch_bounds__(NTHREADS, 1)
void denoise_kernel(const float* __restrict__ images,
                    const float* __restrict__ guidance,
                    const float* __restrict__ estimands,
                    const float* __restrict__ variance,
                    const float* __restrict__ sigma_inv,
                    const int*   __restrict__ spp_ptr,
                    float* __restrict__ out)
{
    extern __shared__ float sm[];
    __shared__ float ssig[9];   // sigma_inv[c] * log2(e)  (for exp2 path)

    const int tid = threadIdx.x;
    const int w0 = blockIdx.x * OW;
    const int h0 = blockIdx.y * OH;
    const int t0 = blockIdx.z * OT;

    if (tid < 9) {
        ssig[tid] = __fmul_rn(sigma_inv[tid], 1.4426950408889634f);
    }
    const float sppf = (float)spp_ptr[0];
    const float T2f  = (float)(2.8070337683438042 * 2.8070337683438042);

    // ---------------- cooperative fill of halo'ed tile (raw values) -------
    // channel c plane at c*PLANE; voxel (y,x) row of HT=16 t-slots with a
    // per-(x,y) slot rotation making warp accesses bank-conflict-free.
    #pragma unroll 6
    for (int it = 0; it < SMEM_FLOATS / NTHREADS; ++it) {  // 294 iters
        int idx = tid + it * NTHREADS;
        int j   = idx & 15;          // local t slot (pre-rotation)
        int rid = idx >> 4;          // (c, y, x)
        int c   = rid / ROWS;
        int yx  = rid - c * ROWS;
        int y   = yx / HX;
        int x   = yx - y * HX;
        int hg = h0 + y - 3;
        int wg = w0 + x - 3;
        int tg_ = t0 + j - 2;
        bool inb = ((unsigned)hg < H) & ((unsigned)wg < W) & ((unsigned)tg_ < T);
        int gidx = (hg * W + wg) * T + tg_;
        float val;
        if (c < 9) {
            val = inb ? guidance[c * HWT + gidx] : 0.0f;
        } else if (c < 12) {
            val = inb ? estimands[(c - 9) * HWT + gidx] : -2.0f;   // pad = -2
        } else if (c < 15) {
            val = inb ? variance[(c - 12) * HWT + gidx] : 0.0f;
        } else {
            val = inb ? images[(c - 15) * HWT + gidx] : 0.0f;
        }
        int slot = (j + ((x >> 1) & 3) + ((y & 3) << 2)) & 15;
        sm[c * PLANE + (y * HX + x) * HT + slot] = val;
    }
    __syncthreads();

    // per-thread copy of guidance scales
    float sigl[9];
    #pragma unroll
    for (int c = 0; c < 9; ++c) sigl[c] = ssig[c];

    // ---------------- per-thread decomposition ----------------
    // warp = fixed tg, ty in a 4-row band, tx 0..7  -> conflict-free LDS
    const int tg  = tid >> 6;
    const int rr  = tid & 63;
    const int ty  = rr >> 3;
    const int tx  = rr & 7;
    const int tg4 = tg * TT;

    // center values (raw) held in registers
    float gc[9][TT], ec[3][TT], vc[3][TT];
    {
        int yc = ty + 3, xc = tx + 3;
        int sxy = ((xc >> 1) & 3) + ((yc & 3) << 2);
        int rowoff = (yc * HX + xc) * HT;
        #pragma unroll
        for (int tt = 0; tt < TT; ++tt) {
            int sl = rowoff + ((tg4 + tt + 2 + sxy) & 15);
            #pragma unroll
            for (int c = 0; c < 9; ++c) gc[c][tt] = sm[c * PLANE + sl];
            #pragma unroll
            for (int c = 0; c < 3; ++c) ec[c][tt] = sm[(9 + c) * PLANE + sl];
            #pragma unroll
            for (int c = 0; c < 3; ++c) vc[c][tt] = sm[(12 + c) * PLANE + sl];
        }
    }

    float num0[TT], num1[TT], num2[TT], den[TT];
    #pragma unroll
    for (int tt = 0; tt < TT; ++tt) { num0[tt] = 0.f; num1[tt] = 0.f; num2[tt] = 0.f; den[tt] = 0.f; }

    // ---------------- main loop over spatial offsets ----------------
    #pragma unroll 1
    for (int dy = 0; dy < 7; ++dy) {
        #pragma unroll 1
        for (int dx = 0; dx < 7; ++dx) {
            int y = ty + dy;
            int x = tx + dx;
            int sxy = ((x >> 1) & 3) + ((y & 3) << 2);
            int rowoff = (y * HX + x) * HT;
            int a[TT + 4];
            #pragma unroll
            for (int jj = 0; jj < TT + 4; ++jj)
                a[jj] = rowoff + ((tg4 + jj + sxy) & 15);

            float nd[TT][5];     // negative log2-scaled distance accumulators
            float fl[TT][5];     // membership failure metric (max over ch)
            #pragma unroll
            for (int tt = 0; tt < TT; ++tt)
                #pragma unroll
                for (int dt = 0; dt < 5; ++dt) { nd[tt][dt] = 0.f; fl[tt][dt] = -1.f; }

            // guidance distance: nd -= sigl[c] * (gn - gc)^2
            #pragma unroll
            for (int c = 0; c < 9; ++c) {
                float row[TT + 4];
                #pragma unroll
                for (int jj = 0; jj < TT + 4; ++jj) row[jj] = sm[c * PLANE + a[jj]];
                float msig = -sigl[c];
                #pragma unroll
                for (int tt = 0; tt < TT; ++tt) {
                    #pragma unroll
                    for (int dt = 0; dt < 5; ++dt) {
                        float d = row[tt + dt] - gc[c][tt];
                        nd[tt][dt] = fmaf(msig, d * d, nd[tt][dt]);
                    }
                }
            }

            // membership z-test, EXACT reference op order (no FMA contraction):
            // fail iff (d*d)*spp > T2*(vn+vc) for any channel
            #pragma unroll
            for (int c = 0; c < 3; ++c) {
                float er[TT + 4], vr[TT + 4];
                #pragma unroll
                for (int jj = 0; jj < TT + 4; ++jj) {
                    er[jj] = sm[(9 + c)  * PLANE + a[jj]];
                    vr[jj] = sm[(12 + c) * PLANE + a[jj]];
                }
                #pragma unroll
                for (int tt = 0; tt < TT; ++tt) {
                    #pragma unroll
                    for (int dt = 0; dt < 5; ++dt) {
                        float d = __fsub_rn(er[tt + dt], ec[c][tt]);
                        float q = __fmul_rn(d, d);
                        float l = __fmul_rn(q, sppf);
                        float s = __fadd_rn(vr[tt + dt], vc[c][tt]);
                        float r = __fmul_rn(T2f, s);
                        fl[tt][dt] = fmaxf(fl[tt][dt], __fsub_rn(l, r));
                    }
                }
            }

            // weights + accumulation
            float i0[TT + 4], i1[TT + 4], i2[TT + 4];
            #pragma unroll
            for (int jj = 0; jj < TT + 4; ++jj) {
                i0[jj] = sm[15 * PLANE + a[jj]];
                i1[jj] = sm[16 * PLANE + a[jj]];
                i2[jj] = sm[17 * PLANE + a[jj]];
            }
            #pragma unroll
            for (int tt = 0; tt < TT; ++tt) {
                #pragma unroll
                for (int dt = 0; dt < 5; ++dt) {
                    // fail > 0 -> weight forced to exactly 0
                    float e = (fl[tt][dt] > 0.0f) ? -350.0f : nd[tt][dt];
                    float wgt;
                    asm("ex2.approx.f32 %0, %1;" : "=f"(wgt) : "f"(e));
                    den[tt]  += wgt;
                    num0[tt] = fmaf(wgt, i0[tt + dt], num0[tt]);
                    num1[tt] = fmaf(wgt, i1[tt + dt], num1[tt]);
                    num2[tt] = fmaf(wgt, i2[tt + dt], num2[tt]);
                }
            }
        }
    }

    // ---------------- write out ----------------
    const int hh = h0 + ty;
    const int ww = w0 + tx;
    #pragma unroll
    for (int tt = 0; tt < TT; ++tt) {
        int t = t0 + tg4 + tt;
        float inv = 1.0f / den[tt];
        int base = (hh * W + ww) * T + t;
        out[base]            = num0[tt] * inv;
        out[HWT + base]      = num1[tt] * inv;
        out[2 * HWT + base]  = num2[tt] * inv;
    }
}

extern "C" void kernel_launch(void* const* d_in, const int* in_sizes, int n_in,
                              void* d_out, int out_size)
{
    const float* images   = (const float*)d_in[0];
    const float* guidance = (const float*)d_in[1];
    const float* estim    = (const float*)d_in[2];
    const float* var      = (const float*)d_in[3];
    const float* sig      = (const float*)d_in[4];
    const int*   spp      = (const int*)d_in[5];
    float* out = (float*)d_out;

    cudaFuncSetAttribute(denoise_kernel,
                         cudaFuncAttributeMaxDynamicSharedMemorySize,
                         SMEM_FLOATS * (int)sizeof(float));

    dim3 grid(W / OW, H / OH, T / OT);   // 32 x 32 x 4
    denoise_kernel<<<grid, NTHREADS, SMEM_FLOATS * sizeof(float)>>>(
        images, guidance, estim, var, sig, spp, out);
}

// round 4
// speedup vs baseline: 1.6853x; 1.6853x over previous
#include <cuda_runtime.h>
#include <math.h>

#define H 256
#define W 256
#define T 48
#define HWT (H*W*T)

// Output tile per block
#define OH 8
#define OW 8
#define OT 12
#define TT 2            // t-outputs per thread (register blocking)
#define NTHREADS 384    // 8 tx * 8 ty(=64) * 6 t-groups

// Halo'ed SMEM tile
#define HY 14           // OH + 6
#define HX 14           // OW + 6
#define HT 16           // OT + 4
#define ROWS (HY*HX)    // 196
#define PLANE (ROWS*HT) // 3136
#define NCH 18          // 9 scaled-guidance + 3 estimands + 3 variance + 3 images
#define SMEM_FLOATS (NCH*PLANE)   // 56448 floats -> 225792 bytes

#define NL (TT + 4)     // 6 t-lanes loaded per row
#define NP (TT * 5)     // 10 (tt,dt) pairs

__global__ __launch_bounds__(NTHREADS, 1)
void denoise_kernel(const float* __restrict__ images,
                    const float* __restrict__ guidance,
                    const float* __restrict__ estimands,
                    const float* __restrict__ variance,
                    const float* __restrict__ sigma_inv,
                    const int*   __restrict__ spp_ptr,
                    float* __restrict__ out)
{
    extern __shared__ float sm[];
    __shared__ float ssig[9];   // sqrt(sigma_inv[c] * log2(e))

    const int tid = threadIdx.x;
    const int w0 = blockIdx.x * OW;
    const int h0 = blockIdx.y * OH;
    const int t0 = blockIdx.z * OT;

    if (tid < 9) {
        ssig[tid] = sqrtf(__fmul_rn(sigma_inv[tid], 1.4426950408889634f));
    }
    const float sppf = (float)spp_ptr[0];
    const float T2f  = (float)(2.8070337683438042 * 2.8070337683438042);
    __syncthreads();

    // ---------------- cooperative fill of halo'ed tile -------------------
    // guidance stored PRE-SCALED: a_c = g_c * sqrt(sigma_c * log2e)
    // estimands / variance / images stored RAW (z-test must be bit-exact).
    // voxel (y,x) row of HT=16 t-slots with per-(x,y) slot rotation making
    // warp accesses bank-conflict-free.
    #pragma unroll 7
    for (int it = 0; it < SMEM_FLOATS / NTHREADS; ++it) {  // 147 iters
        int idx = tid + it * NTHREADS;
        int j   = idx & 15;          // local t slot (pre-rotation)
        int rid = idx >> 4;          // (c, y, x)
        int c   = rid / ROWS;
        int yx  = rid - c * ROWS;
        int y   = yx / HX;
        int x   = yx - y * HX;
        int hg = h0 + y - 3;
        int wg = w0 + x - 3;
        int tg_ = t0 + j - 2;
        bool inb = ((unsigned)hg < H) & ((unsigned)wg < W) & ((unsigned)tg_ < T);
        int gidx = (hg * W + wg) * T + tg_;
        float val;
        if (c < 9) {
            val = inb ? guidance[c * HWT + gidx] * ssig[c] : 0.0f;
        } else if (c < 12) {
            val = inb ? estimands[(c - 9) * HWT + gidx] : -2.0f;   // pad = -2
        } else if (c < 15) {
            val = inb ? variance[(c - 12) * HWT + gidx] : 0.0f;
        } else {
            val = inb ? images[(c - 15) * HWT + gidx] : 0.0f;
        }
        int slot = (j + ((x >> 1) & 3) + ((y & 3) << 2)) & 15;
        sm[c * PLANE + (y * HX + x) * HT + slot] = val;
    }
    __syncthreads();

    // ---------------- per-thread decomposition ----------------
    // warp = {ty 0..3 or 4..7} x {tx 0..7}, fixed tg  -> conflict-free LDS
    const int tg  = tid >> 6;          // 0..5
    const int rr  = tid & 63;
    const int ty  = rr >> 3;
    const int tx  = rr & 7;
    const int tgb = tg * TT;

    // center values held in registers
    float gc[9][TT], ec[3][TT], vc[3][TT], Pc[TT];
    {
        int yc = ty + 3, xc = tx + 3;
        int sxy = ((xc >> 1) & 3) + ((yc & 3) << 2);
        int rowoff = (yc * HX + xc) * HT;
        #pragma unroll
        for (int tt = 0; tt < TT; ++tt) {
            int sl = rowoff + ((tgb + tt + 2 + sxy) & 15);
            float p = 0.0f;
            #pragma unroll
            for (int c = 0; c < 9; ++c) {
                float a = sm[c * PLANE + sl];
                gc[c][tt] = a;
                p = fmaf(a, a, p);           // same chain order as P_j below
            }
            Pc[tt] = p;
            #pragma unroll
            for (int c = 0; c < 3; ++c) ec[c][tt] = sm[(9 + c) * PLANE + sl];
            #pragma unroll
            for (int c = 0; c < 3; ++c) vc[c][tt] = sm[(12 + c) * PLANE + sl];
        }
    }

    float num0[TT], num1[TT], num2[TT], den[TT];
    #pragma unroll
    for (int tt = 0; tt < TT; ++tt) { num0[tt] = 0.f; num1[tt] = 0.f; num2[tt] = 0.f; den[tt] = 0.f; }

    // ---------------- main loop over spatial offsets ----------------
    #pragma unroll 1
    for (int dy = 0; dy < 7; ++dy) {
        #pragma unroll 1
        for (int dx = 0; dx < 7; ++dx) {
            int y = ty + dy;
            int x = tx + dx;
            int sxy = ((x >> 1) & 3) + ((y & 3) << 2);
            int rowoff = (y * HX + x) * HT;
            int a[NL];
            #pragma unroll
            for (int jj = 0; jj < NL; ++jj)
                a[jj] = rowoff + ((tgb + jj + sxy) & 15);

            // guidance: dot products + on-the-fly neighbor norms
            float Pn[NL];
            float dot[TT][5];
            #pragma unroll
            for (int jj = 0; jj < NL; ++jj) Pn[jj] = 0.f;
            #pragma unroll
            for (int tt = 0; tt < TT; ++tt)
                #pragma unroll
                for (int dt = 0; dt < 5; ++dt) dot[tt][dt] = 0.f;

            #pragma unroll
            for (int c = 0; c < 9; ++c) {
                float row[NL];
                #pragma unroll
                for (int jj = 0; jj < NL; ++jj) row[jj] = sm[c * PLANE + a[jj]];
                #pragma unroll
                for (int jj = 0; jj < NL; ++jj) Pn[jj] = fmaf(row[jj], row[jj], Pn[jj]);
                #pragma unroll
                for (int tt = 0; tt < TT; ++tt)
                    #pragma unroll
                    for (int dt = 0; dt < 5; ++dt)
                        dot[tt][dt] = fmaf(row[tt + dt], gc[c][tt], dot[tt][dt]);
            }

            // membership z-test, EXACT reference op order (no FMA contraction):
            // fail iff (d*d)*spp > T2*(vn+vc) for any channel
            float fl[TT][5];
            #pragma unroll
            for (int tt = 0; tt < TT; ++tt)
                #pragma unroll
                for (int dt = 0; dt < 5; ++dt) fl[tt][dt] = -1.f;

            #pragma unroll
            for (int c = 0; c < 3; ++c) {
                float er[NL], vr[NL];
                #pragma unroll
                for (int jj = 0; jj < NL; ++jj) {
                    er[jj] = sm[(9 + c)  * PLANE + a[jj]];
                    vr[jj] = sm[(12 + c) * PLANE + a[jj]];
                }
                #pragma unroll
                for (int tt = 0; tt < TT; ++tt) {
                    #pragma unroll
                    for (int dt = 0; dt < 5; ++dt) {
                        float d = __fsub_rn(er[tt + dt], ec[c][tt]);
                        float q = __fmul_rn(d, d);
                        float l = __fmul_rn(q, sppf);
                        float s = __fadd_rn(vr[tt + dt], vc[c][tt]);
                        float r = __fmul_rn(T2f, s);
                        fl[tt][dt] = fmaxf(fl[tt][dt], __fsub_rn(l, r));
                    }
                }
            }

            // weights + accumulation
            float i0[NL], i1[NL], i2[NL];
            #pragma unroll
            for (int jj = 0; jj < NL; ++jj) {
                i0[jj] = sm[15 * PLANE + a[jj]];
                i1[jj] = sm[16 * PLANE + a[jj]];
                i2[jj] = sm[17 * PLANE + a[jj]];
            }
            #pragma unroll
            for (int tt = 0; tt < TT; ++tt) {
                #pragma unroll
                for (int dt = 0; dt < 5; ++dt) {
                    // exp2 argument: 2*dot - Pn - Pc  (== -sum sig*log2e*(gn-gc)^2)
                    float psum = Pn[tt + dt] + Pc[tt];
                    float e = fmaf(2.0f, dot[tt][dt], -psum);
                    // fail > 0 -> weight forced to exactly 0
                    e = (fl[tt][dt] > 0.0f) ? -350.0f : e;
                    float wgt;
                    asm("ex2.approx.f32 %0, %1;" : "=f"(wgt) : "f"(e));
                    den[tt]  += wgt;
                    num0[tt] = fmaf(wgt, i0[tt + dt], num0[tt]);
                    num1[tt] = fmaf(wgt, i1[tt + dt], num1[tt]);
                    num2[tt] = fmaf(wgt, i2[tt + dt], num2[tt]);
                }
            }
        }
    }

    // ---------------- write out ----------------
    const int hh = h0 + ty;
    const int ww = w0 + tx;
    #pragma unroll
    for (int tt = 0; tt < TT; ++tt) {
        int t = t0 + tgb + tt;
        float inv = 1.0f / den[tt];
        int base = (hh * W + ww) * T + t;
        out[base]            = num0[tt] * inv;
        out[HWT + base]      = num1[tt] * inv;
        out[2 * HWT + base]  = num2[tt] * inv;
    }
}

extern "C" void kernel_launch(void* const* d_in, const int* in_sizes, int n_in,
                              void* d_out, int out_size)
{
    const float* images   = (const float*)d_in[0];
    const float* guidance = (const float*)d_in[1];
    const float* estim    = (const float*)d_in[2];
    const float* var      = (const float*)d_in[3];
    const float* sig      = (const float*)d_in[4];
    const int*   spp      = (const int*)d_in[5];
    float* out = (float*)d_out;

    cudaFuncSetAttribute(denoise_kernel,
                         cudaFuncAttributeMaxDynamicSharedMemorySize,
                         SMEM_FLOATS * (int)sizeof(float));

    dim3 grid(W / OW, H / OH, T / OT);   // 32 x 32 x 4
    denoise_kernel<<<grid, NTHREADS, SMEM_FLOATS * sizeof(float)>>>(
        images, guidance, estim, var, sig, spp, out);
}

// round 5
// speedup vs baseline: 2.0815x; 1.2351x over previous
#include <cuda_runtime.h>
#include <math.h>

#define H 256
#define W 256
#define T 48
#define HWT (H*W*T)

// Output tile per block
#define OH 8
#define OW 8
#define OT 12
#define TT 2            // t-outputs per thread (register blocking)
#define NTHREADS 768    // 2 offset-groups x (8 tx * 8 ty * 6 tg)

// Halo'ed SMEM tile
#define HY 14           // OH + 6
#define HX 14           // OW + 6
#define HT 16           // OT + 4
#define ROWS (HY*HX)    // 196
#define PLANE (ROWS*HT) // 3136
#define NCH 18          // 9 scaled-guidance + 3 estimands + 3 variance + 3 images
#define SMEM_FLOATS (NCH*PLANE)   // 56448 floats -> 225792 bytes

#define NL (TT + 4)     // 6 t-lanes loaded per row

__global__ __launch_bounds__(NTHREADS, 1)
void denoise_kernel(const float* __restrict__ images,
                    const float* __restrict__ guidance,
                    const float* __restrict__ estimands,
                    const float* __restrict__ variance,
                    const float* __restrict__ sigma_inv,
                    const int*   __restrict__ spp_ptr,
                    float* __restrict__ out)
{
    extern __shared__ float sm[];
    __shared__ float ssig[9];   // sqrt(sigma_inv[c] * log2(e))

    const int tid = threadIdx.x;
    const int w0 = blockIdx.x * OW;
    const int h0 = blockIdx.y * OH;
    const int t0 = blockIdx.z * OT;

    if (tid < 9) {
        ssig[tid] = sqrtf(__fmul_rn(sigma_inv[tid], 1.4426950408889634f));
    }
    const float sppf = (float)spp_ptr[0];
    const float T2f  = (float)(2.8070337683438042 * 2.8070337683438042);
    __syncthreads();

    // ---------------- cooperative fill of halo'ed tile -------------------
    // guidance stored PRE-SCALED: a_c = g_c * sqrt(sigma_c * log2e)
    // estimands / variance / images stored RAW (z-test must be bit-exact).
    // voxel (y,x) row of HT=16 t-slots with per-(x,y) slot rotation making
    // warp accesses bank-conflict-free.
    #pragma unroll 4
    for (int it = 0; it < (SMEM_FLOATS + NTHREADS - 1) / NTHREADS; ++it) {  // 74 iters
        int idx = tid + it * NTHREADS;
        if (idx < SMEM_FLOATS) {
            int j   = idx & 15;          // local t slot (pre-rotation)
            int rid = idx >> 4;          // (c, y, x)
            int c   = rid / ROWS;
            int yx  = rid - c * ROWS;
            int y   = yx / HX;
            int x   = yx - y * HX;
            int hg = h0 + y - 3;
            int wg = w0 + x - 3;
            int tg_ = t0 + j - 2;
            bool inb = ((unsigned)hg < H) & ((unsigned)wg < W) & ((unsigned)tg_ < T);
            int gidx = (hg * W + wg) * T + tg_;
            float val;
            if (c < 9) {
                val = inb ? guidance[c * HWT + gidx] * ssig[c] : 0.0f;
            } else if (c < 12) {
                val = inb ? estimands[(c - 9) * HWT + gidx] : -2.0f;   // pad = -2
            } else if (c < 15) {
                val = inb ? variance[(c - 12) * HWT + gidx] : 0.0f;
            } else {
                val = inb ? images[(c - 15) * HWT + gidx] : 0.0f;
            }
            int slot = (j + ((x >> 1) & 3) + ((y & 3) << 2)) & 15;
            sm[c * PLANE + (y * HX + x) * HT + slot] = val;
        }
    }
    __syncthreads();

    // ---------------- per-thread decomposition ----------------
    // two offset-groups; within a group: warp = {4 ty rows} x {tx 0..7},
    // fixed tg  -> conflict-free LDS (same shape for both groups)
    const int og  = (tid >= 384) ? 1 : 0;
    const int lt  = tid - og * 384;
    const int tg  = lt >> 6;          // 0..5
    const int rr  = lt & 63;
    const int ty  = rr >> 3;
    const int tx  = rr & 7;
    const int tgb = tg * TT;
    const int o0  = og ? 25 : 0;      // spatial-offset range [o0, o1)
    const int o1  = og ? 49 : 25;

    // center values held in registers
    float gc[9][TT], ec[3][TT], vc[3][TT], Pc[TT];
    {
        int yc = ty + 3, xc = tx + 3;
        int sxy = ((xc >> 1) & 3) + ((yc & 3) << 2);
        int rowoff = (yc * HX + xc) * HT;
        #pragma unroll
        for (int tt = 0; tt < TT; ++tt) {
            int sl = rowoff + ((tgb + tt + 2 + sxy) & 15);
            float p = 0.0f;
            #pragma unroll
            for (int c = 0; c < 9; ++c) {
                float a = sm[c * PLANE + sl];
                gc[c][tt] = a;
                p = fmaf(a, a, p);           // same chain order as P_j below
            }
            Pc[tt] = p;
            #pragma unroll
            for (int c = 0; c < 3; ++c) ec[c][tt] = sm[(9 + c) * PLANE + sl];
            #pragma unroll
            for (int c = 0; c < 3; ++c) vc[c][tt] = sm[(12 + c) * PLANE + sl];
        }
    }

    float num0[TT], num1[TT], num2[TT], den[TT];
    #pragma unroll
    for (int tt = 0; tt < TT; ++tt) { num0[tt] = 0.f; num1[tt] = 0.f; num2[tt] = 0.f; den[tt] = 0.f; }

    // ---------------- main loop over this group's spatial offsets --------
    #pragma unroll 1
    for (int o = o0; o < o1; ++o) {
        int dy = o / 7;
        int dx = o - dy * 7;
        int y = ty + dy;
        int x = tx + dx;
        int sxy = ((x >> 1) & 3) + ((y & 3) << 2);
        int rowoff = (y * HX + x) * HT;
        int a[NL];
        #pragma unroll
        for (int jj = 0; jj < NL; ++jj)
            a[jj] = rowoff + ((tgb + jj + sxy) & 15);

        // guidance: dot products + on-the-fly neighbor norms
        float Pn[NL];
        float dot[TT][5];
        #pragma unroll
        for (int jj = 0; jj < NL; ++jj) Pn[jj] = 0.f;
        #pragma unroll
        for (int tt = 0; tt < TT; ++tt)
            #pragma unroll
            for (int dt = 0; dt < 5; ++dt) dot[tt][dt] = 0.f;

        #pragma unroll
        for (int c = 0; c < 9; ++c) {
            float row[NL];
            #pragma unroll
            for (int jj = 0; jj < NL; ++jj) row[jj] = sm[c * PLANE + a[jj]];
            #pragma unroll
            for (int jj = 0; jj < NL; ++jj) Pn[jj] = fmaf(row[jj], row[jj], Pn[jj]);
            #pragma unroll
            for (int tt = 0; tt < TT; ++tt)
                #pragma unroll
                for (int dt = 0; dt < 5; ++dt)
                    dot[tt][dt] = fmaf(row[tt + dt], gc[c][tt], dot[tt][dt]);
        }

        // membership z-test, EXACT reference op order (no FMA contraction):
        // fail iff (d*d)*spp > T2*(vn+vc) for any channel
        float fl[TT][5];
        #pragma unroll
        for (int tt = 0; tt < TT; ++tt)
            #pragma unroll
            for (int dt = 0; dt < 5; ++dt) fl[tt][dt] = -1.f;

        #pragma unroll
        for (int c = 0; c < 3; ++c) {
            float er[NL], vr[NL];
            #pragma unroll
            for (int jj = 0; jj < NL; ++jj) {
                er[jj] = sm[(9 + c)  * PLANE + a[jj]];
                vr[jj] = sm[(12 + c) * PLANE + a[jj]];
            }
            #pragma unroll
            for (int tt = 0; tt < TT; ++tt) {
                #pragma unroll
                for (int dt = 0; dt < 5; ++dt) {
                    float d = __fsub_rn(er[tt + dt], ec[c][tt]);
                    float q = __fmul_rn(d, d);
                    float l = __fmul_rn(q, sppf);
                    float s = __fadd_rn(vr[tt + dt], vc[c][tt]);
                    float r = __fmul_rn(T2f, s);
                    fl[tt][dt] = fmaxf(fl[tt][dt], __fsub_rn(l, r));
                }
            }
        }

        // weights + accumulation
        float i0[NL], i1[NL], i2[NL];
        #pragma unroll
        for (int jj = 0; jj < NL; ++jj) {
            i0[jj] = sm[15 * PLANE + a[jj]];
            i1[jj] = sm[16 * PLANE + a[jj]];
            i2[jj] = sm[17 * PLANE + a[jj]];
        }
        #pragma unroll
        for (int tt = 0; tt < TT; ++tt) {
            #pragma unroll
            for (int dt = 0; dt < 5; ++dt) {
                // exp2 argument: 2*dot - Pn - Pc  (== -sum sig*log2e*(gn-gc)^2)
                float psum = Pn[tt + dt] + Pc[tt];
                float e = fmaf(2.0f, dot[tt][dt], -psum);
                // fail > 0 -> weight forced to exactly 0
                e = (fl[tt][dt] > 0.0f) ? -350.0f : e;
                float wgt;
                asm("ex2.approx.f32 %0, %1;" : "=f"(wgt) : "f"(e));
                den[tt]  += wgt;
                num0[tt] = fmaf(wgt, i0[tt + dt], num0[tt]);
                num1[tt] = fmaf(wgt, i1[tt + dt], num1[tt]);
                num2[tt] = fmaf(wgt, i2[tt + dt], num2[tt]);
            }
        }
    }

    // ---------------- cross-group reduction through smem -----------------
    __syncthreads();   // everyone done reading the tile
    if (og) {
        int p = lt * 9;                 // stride 9: conflict-light
        sm[p + 0] = num0[0]; sm[p + 1] = num0[1];
        sm[p + 2] = num1[0]; sm[p + 3] = num1[1];
        sm[p + 4] = num2[0]; sm[p + 5] = num2[1];
        sm[p + 6] = den[0];  sm[p + 7] = den[1];
    }
    __syncthreads();

    // ---------------- write out (group A only) ----------------
    if (!og) {
        int p = lt * 9;
        num0[0] += sm[p + 0]; num0[1] += sm[p + 1];
        num1[0] += sm[p + 2]; num1[1] += sm[p + 3];
        num2[0] += sm[p + 4]; num2[1] += sm[p + 5];
        den[0]  += sm[p + 6]; den[1]  += sm[p + 7];

        const int hh = h0 + ty;
        const int ww = w0 + tx;
        #pragma unroll
        for (int tt = 0; tt < TT; ++tt) {
            int t = t0 + tgb + tt;
            float inv = 1.0f / den[tt];
            int base = (hh * W + ww) * T + t;
            out[base]            = num0[tt] * inv;
            out[HWT + base]      = num1[tt] * inv;
            out[2 * HWT + base]  = num2[tt] * inv;
        }
    }
}

extern "C" void kernel_launch(void* const* d_in, const int* in_sizes, int n_in,
                              void* d_out, int out_size)
{
    const float* images   = (const float*)d_in[0];
    const float* guidance = (const float*)d_in[1];
    const float* estim    = (const float*)d_in[2];
    const float* var      = (const float*)d_in[3];
    const float* sig      = (const float*)d_in[4];
    const int*   spp      = (const int*)d_in[5];
    float* out = (float*)d_out;

    cudaFuncSetAttribute(denoise_kernel,
                         cudaFuncAttributeMaxDynamicSharedMemorySize,
                         SMEM_FLOATS * (int)sizeof(float));

    dim3 grid(W / OW, H / OH, T / OT);   // 32 x 32 x 4
    denoise_kernel<<<grid, NTHREADS, SMEM_FLOATS * sizeof(float)>>>(
        images, guidance, estim, var, sig, spp, out);
}

// round 6
// speedup vs baseline: 2.7125x; 1.3031x over previous
#include <cuda_runtime.h>
#include <math.h>

#define H 256
#define W 256
#define T 48
#define HWT (H*W*T)

// Output tile per block
#define OH 8
#define OW 8
#define OT 12
#define TT 2            // t-outputs per thread (register blocking)
#define NTHREADS 768    // 2 offset-groups x (8 tx * 8 ty * 6 tg)

// Halo'ed SMEM tile
#define HY 14           // OH + 6
#define HX 14           // OW + 6
#define HT 16           // OT + 4
#define ROWS (HY*HX)    // 196
#define PLANE (ROWS*HT) // 3136
#define NCH 18          // 9 scaled-guidance + 3 estimands + 3 variance + 3 images
#define SMEM_FLOATS (NCH*PLANE)   // 56448 floats -> 225792 bytes
#define SMEM_PAIRS (SMEM_FLOATS/2)

#define NL (TT + 4)     // 6 t-lanes loaded per row

// even rotation: keeps (jj, jj+1) pairs 8B-aligned & contiguous, and gives
// per-phase (16-lane) bank-conflict freedom for LDS.64
#define PHI2(x, y) (((((x) >> 1) & 3) + (((y) & 1) << 2)) << 1)

__global__ __launch_bounds__(NTHREADS, 1)
void denoise_kernel(const float* __restrict__ images,
                    const float* __restrict__ guidance,
                    const float* __restrict__ estimands,
                    const float* __restrict__ variance,
                    const float* __restrict__ sigma_inv,
                    const int*   __restrict__ spp_ptr,
                    float* __restrict__ out)
{
    extern __shared__ float sm[];
    __shared__ float ssig[9];   // sqrt(sigma_inv[c] * log2(e))

    const int tid = threadIdx.x;
    const int w0 = blockIdx.x * OW;
    const int h0 = blockIdx.y * OH;
    const int t0 = blockIdx.z * OT;

    if (tid < 9) {
        ssig[tid] = sqrtf(__fmul_rn(sigma_inv[tid], 1.4426950408889634f));
    }
    const float sppf = (float)spp_ptr[0];
    const float T2f  = (float)(2.8070337683438042 * 2.8070337683438042);
    __syncthreads();

    // ---------------- cooperative fill of halo'ed tile (paired) ----------
    // guidance stored PRE-SCALED: a_c = g_c * sqrt(sigma_c * log2e)
    // estimands / variance / images stored RAW (z-test must be bit-exact).
    // Each thread handles a t-pair (j, j+1). t-bounds are pair-uniform
    // because t0 and T are even.
    #pragma unroll 4
    for (int it = 0; it < (SMEM_PAIRS + NTHREADS - 1) / NTHREADS; ++it) {  // 37 iters
        int idx = tid + it * NTHREADS;
        if (idx < SMEM_PAIRS) {
            int jp  = idx & 7;           // pair index in row
            int j   = jp << 1;           // even t slot (pre-rotation)
            int rid = idx >> 3;          // (c, y, x)
            int c   = rid / ROWS;
            int yx  = rid - c * ROWS;
            int y   = yx / HX;
            int x   = yx - y * HX;
            int hg = h0 + y - 3;
            int wg = w0 + x - 3;
            int tg_ = t0 + j - 2;        // even
            bool inb = ((unsigned)hg < H) & ((unsigned)wg < W) & ((unsigned)tg_ < T);
            int gidx = (hg * W + wg) * T + tg_;
            float2 val;
            if (c < 9) {
                if (inb) {
                    float2 g = *(const float2*)(guidance + c * HWT + gidx);
                    val.x = g.x * ssig[c]; val.y = g.y * ssig[c];
                } else { val.x = 0.f; val.y = 0.f; }
            } else if (c < 12) {
                if (inb) val = *(const float2*)(estimands + (c - 9) * HWT + gidx);
                else     { val.x = -2.f; val.y = -2.f; }
            } else if (c < 15) {
                if (inb) val = *(const float2*)(variance + (c - 12) * HWT + gidx);
                else     { val.x = 0.f; val.y = 0.f; }
            } else {
                if (inb) val = *(const float2*)(images + (c - 15) * HWT + gidx);
                else     { val.x = 0.f; val.y = 0.f; }
            }
            int slot = (j + PHI2(x, y)) & 15;    // even -> 8B aligned
            *(float2*)(sm + c * PLANE + (y * HX + x) * HT + slot) = val;
        }
    }
    __syncthreads();

    // ---------------- per-thread decomposition ----------------
    const int og  = (tid >= 384) ? 1 : 0;
    const int lt  = tid - og * 384;
    const int tg  = lt >> 6;          // 0..5
    const int rr  = lt & 63;
    const int ty  = rr >> 3;
    const int tx  = rr & 7;
    const int tgb = tg * TT;          // even
    const int o0  = og ? 25 : 0;      // spatial-offset range [o0, o1)
    const int o1  = og ? 49 : 25;

    // center values held in registers
    float gc[9][TT], ec[3][TT], vc[3][TT], Pc[TT];
    {
        int yc = ty + 3, xc = tx + 3;
        int ph = PHI2(xc, yc);
        int rowoff = (yc * HX + xc) * HT;
        #pragma unroll
        for (int tt = 0; tt < TT; ++tt) {
            int sl = rowoff + ((tgb + tt + 2 + ph) & 15);
            float p = 0.0f;
            #pragma unroll
            for (int c = 0; c < 9; ++c) {
                float a = sm[c * PLANE + sl];
                gc[c][tt] = a;
                p = fmaf(a, a, p);           // same chain order as P_j below
            }
            Pc[tt] = p;
            #pragma unroll
            for (int c = 0; c < 3; ++c) ec[c][tt] = sm[(9 + c) * PLANE + sl];
            #pragma unroll
            for (int c = 0; c < 3; ++c) vc[c][tt] = sm[(12 + c) * PLANE + sl];
        }
    }

    float num0[TT], num1[TT], num2[TT], den[TT];
    #pragma unroll
    for (int tt = 0; tt < TT; ++tt) { num0[tt] = 0.f; num1[tt] = 0.f; num2[tt] = 0.f; den[tt] = 0.f; }

    // ---------------- main loop over this group's spatial offsets --------
    int dy = o0 / 7, dx = o0 - 7 * (o0 / 7);
    #pragma unroll 1
    for (int o = o0; o < o1; ++o) {
        int y = ty + dy;
        int x = tx + dx;
        int rowoff = (y * HX + x) * HT;
        int ph = PHI2(x, y);
        // three even pair bases, contiguous 8B each (wrap never splits a pair)
        int p0 = rowoff + ((tgb + 0 + ph) & 15);
        int p1 = rowoff + ((tgb + 2 + ph) & 15);
        int p2 = rowoff + ((tgb + 4 + ph) & 15);

        // guidance: dot products + on-the-fly neighbor norms
        float Pn[NL];
        float dot[TT][5];
        #pragma unroll
        for (int jj = 0; jj < NL; ++jj) Pn[jj] = 0.f;
        #pragma unroll
        for (int tt = 0; tt < TT; ++tt)
            #pragma unroll
            for (int dt = 0; dt < 5; ++dt) dot[tt][dt] = 0.f;

        #pragma unroll
        for (int c = 0; c < 9; ++c) {
            const float* sc = sm + c * PLANE;
            float2 r0 = *(const float2*)(sc + p0);
            float2 r1 = *(const float2*)(sc + p1);
            float2 r2 = *(const float2*)(sc + p2);
            float row[NL] = { r0.x, r0.y, r1.x, r1.y, r2.x, r2.y };
            #pragma unroll
            for (int jj = 0; jj < NL; ++jj) Pn[jj] = fmaf(row[jj], row[jj], Pn[jj]);
            #pragma unroll
            for (int tt = 0; tt < TT; ++tt)
                #pragma unroll
                for (int dt = 0; dt < 5; ++dt)
                    dot[tt][dt] = fmaf(row[tt + dt], gc[c][tt], dot[tt][dt]);
        }

        // membership z-test, EXACT reference op order (no FMA contraction):
        // fail iff (d*d)*spp > T2*(vn+vc) for any channel
        float fl[TT][5];
        #pragma unroll
        for (int tt = 0; tt < TT; ++tt)
            #pragma unroll
            for (int dt = 0; dt < 5; ++dt) fl[tt][dt] = -1.f;

        #pragma unroll
        for (int c = 0; c < 3; ++c) {
            const float* se = sm + (9 + c)  * PLANE;
            const float* sv = sm + (12 + c) * PLANE;
            float2 e0 = *(const float2*)(se + p0);
            float2 e1 = *(const float2*)(se + p1);
            float2 e2 = *(const float2*)(se + p2);
            float2 v0 = *(const float2*)(sv + p0);
            float2 v1 = *(const float2*)(sv + p1);
            float2 v2 = *(const float2*)(sv + p2);
            float er[NL] = { e0.x, e0.y, e1.x, e1.y, e2.x, e2.y };
            float vr[NL] = { v0.x, v0.y, v1.x, v1.y, v2.x, v2.y };
            #pragma unroll
            for (int tt = 0; tt < TT; ++tt) {
                #pragma unroll
                for (int dt = 0; dt < 5; ++dt) {
                    float d = __fsub_rn(er[tt + dt], ec[c][tt]);
                    float q = __fmul_rn(d, d);
                    float l = __fmul_rn(q, sppf);
                    float s = __fadd_rn(vr[tt + dt], vc[c][tt]);
                    float r = __fmul_rn(T2f, s);
                    fl[tt][dt] = fmaxf(fl[tt][dt], __fsub_rn(l, r));
                }
            }
        }

        // weights + accumulation
        float i0[NL], i1[NL], i2[NL];
        {
            const float* s0 = sm + 15 * PLANE;
            const float* s1 = sm + 16 * PLANE;
            const float* s2 = sm + 17 * PLANE;
            float2 a0 = *(const float2*)(s0 + p0);
            float2 a1 = *(const float2*)(s0 + p1);
            float2 a2 = *(const float2*)(s0 + p2);
            i0[0]=a0.x; i0[1]=a0.y; i0[2]=a1.x; i0[3]=a1.y; i0[4]=a2.x; i0[5]=a2.y;
            float2 b0 = *(const float2*)(s1 + p0);
            float2 b1 = *(const float2*)(s1 + p1);
            float2 b2 = *(const float2*)(s1 + p2);
            i1[0]=b0.x; i1[1]=b0.y; i1[2]=b1.x; i1[3]=b1.y; i1[4]=b2.x; i1[5]=b2.y;
            float2 c0 = *(const float2*)(s2 + p0);
            float2 c1 = *(const float2*)(s2 + p1);
            float2 c2 = *(const float2*)(s2 + p2);
            i2[0]=c0.x; i2[1]=c0.y; i2[2]=c1.x; i2[3]=c1.y; i2[4]=c2.x; i2[5]=c2.y;
        }
        #pragma unroll
        for (int tt = 0; tt < TT; ++tt) {
            #pragma unroll
            for (int dt = 0; dt < 5; ++dt) {
                // exp2 argument: 2*dot - Pn - Pc  (== -sum sig*log2e*(gn-gc)^2)
                float psum = Pn[tt + dt] + Pc[tt];
                float e = fmaf(2.0f, dot[tt][dt], -psum);
                // fail > 0 -> weight forced to exactly 0
                e = (fl[tt][dt] > 0.0f) ? -350.0f : e;
                float wgt;
                asm("ex2.approx.f32 %0, %1;" : "=f"(wgt) : "f"(e));
                den[tt]  += wgt;
                num0[tt] = fmaf(wgt, i0[tt + dt], num0[tt]);
                num1[tt] = fmaf(wgt, i1[tt + dt], num1[tt]);
                num2[tt] = fmaf(wgt, i2[tt + dt], num2[tt]);
            }
        }

        if (++dx == 7) { dx = 0; ++dy; }
    }

    // ---------------- cross-group reduction through smem -----------------
    __syncthreads();   // everyone done reading the tile
    if (og) {
        int p = lt * 9;                 // stride 9: conflict-light
        sm[p + 0] = num0[0]; sm[p + 1] = num0[1];
        sm[p + 2] = num1[0]; sm[p + 3] = num1[1];
        sm[p + 4] = num2[0]; sm[p + 5] = num2[1];
        sm[p + 6] = den[0];  sm[p + 7] = den[1];
    }
    __syncthreads();

    // ---------------- write out (group A only) ----------------
    if (!og) {
        int p = lt * 9;
        num0[0] += sm[p + 0]; num0[1] += sm[p + 1];
        num1[0] += sm[p + 2]; num1[1] += sm[p + 3];
        num2[0] += sm[p + 4]; num2[1] += sm[p + 5];
        den[0]  += sm[p + 6]; den[1]  += sm[p + 7];

        const int hh = h0 + ty;
        const int ww = w0 + tx;
        #pragma unroll
        for (int tt = 0; tt < TT; ++tt) {
            int t = t0 + tgb + tt;
            float inv = 1.0f / den[tt];
            int base = (hh * W + ww) * T + t;
            out[base]            = num0[tt] * inv;
            out[HWT + base]      = num1[tt] * inv;
            out[2 * HWT + base]  = num2[tt] * inv;
        }
    }
}

extern "C" void kernel_launch(void* const* d_in, const int* in_sizes, int n_in,
                              void* d_out, int out_size)
{
    const float* images   = (const float*)d_in[0];
    const float* guidance = (const float*)d_in[1];
    const float* estim    = (const float*)d_in[2];
    const float* var      = (const float*)d_in[3];
    const float* sig      = (const float*)d_in[4];
    const int*   spp      = (const int*)d_in[5];
    float* out = (float*)d_out;

    cudaFuncSetAttribute(denoise_kernel,
                         cudaFuncAttributeMaxDynamicSharedMemorySize,
                         SMEM_FLOATS * (int)sizeof(float));

    dim3 grid(W / OW, H / OH, T / OT);   // 32 x 32 x 4
    denoise_kernel<<<grid, NTHREADS, SMEM_FLOATS * sizeof(float)>>>(
        images, guidance, estim, var, sig, spp, out);
}

// round 7
// speedup vs baseline: 2.7231x; 1.0039x over previous
#include <cuda_runtime.h>
#include <math.h>

#define H 256
#define W 256
#define T 48
#define HWT (H*W*T)

// Output tile per block
#define OH 8
#define OW 8
#define OT 12
#define TT 2            // t-outputs per thread (register blocking)
#define NTHREADS 768    // 2 offset-groups x (8 tx * 8 ty * 6 tg)

// Halo'ed SMEM tile
#define HY 14           // OH + 6
#define HX 14           // OW + 6
#define HT 16           // OT + 4
#define ROWS (HY*HX)    // 196
#define PLANE (ROWS*HT) // 3136
#define NCH 18          // 9 scaled-guidance + 3 estimands + 3 variance + 3 images
#define SMEM_FLOATS (NCH*PLANE)   // 56448 floats -> 225792 bytes
#define SMEM_PAIRS (SMEM_FLOATS/2)

#define NL (TT + 4)     // 6 t-lanes loaded per row

// even rotation: keeps (jj, jj+1) pairs 8B-aligned & contiguous, and gives
// per-phase (16-lane) bank-conflict freedom for LDS.64
#define PHI2(x, y) (((((x) >> 1) & 3) + (((y) & 1) << 2)) << 1)

__global__ __launch_bounds__(NTHREADS, 1)
void denoise_kernel(const float* __restrict__ images,
                    const float* __restrict__ guidance,
                    const float* __restrict__ estimands,
                    const float* __restrict__ variance,
                    const float* __restrict__ sigma_inv,
                    const int*   __restrict__ spp_ptr,
                    float* __restrict__ out)
{
    extern __shared__ float sm[];
    __shared__ float ssig[9];   // sqrt(sigma_inv[c] * log2(e))

    const int tid = threadIdx.x;
    const int w0 = blockIdx.x * OW;
    const int h0 = blockIdx.y * OH;
    const int t0 = blockIdx.z * OT;

    if (tid < 9) {
        ssig[tid] = sqrtf(__fmul_rn(sigma_inv[tid], 1.4426950408889634f));
    }
    const float sppf = (float)spp_ptr[0];
    const float T2f  = (float)(2.8070337683438042 * 2.8070337683438042);
    __syncthreads();

    // ---------------- cooperative fill of halo'ed tile (paired) ----------
    // guidance stored PRE-SCALED: a_c = g_c * sqrt(sigma_c * log2e)
    // estimands / variance / images stored RAW (z-test must be bit-exact).
    // Each thread handles a t-pair (j, j+1). t-bounds are pair-uniform
    // because t0 and T are even.
    #pragma unroll 4
    for (int it = 0; it < (SMEM_PAIRS + NTHREADS - 1) / NTHREADS; ++it) {  // 37 iters
        int idx = tid + it * NTHREADS;
        if (idx < SMEM_PAIRS) {
            int jp  = idx & 7;           // pair index in row
            int j   = jp << 1;           // even t slot (pre-rotation)
            int rid = idx >> 3;          // (c, y, x)
            int c   = rid / ROWS;
            int yx  = rid - c * ROWS;
            int y   = yx / HX;
            int x   = yx - y * HX;
            int hg = h0 + y - 3;
            int wg = w0 + x - 3;
            int tg_ = t0 + j - 2;        // even
            bool inb = ((unsigned)hg < H) & ((unsigned)wg < W) & ((unsigned)tg_ < T);
            int gidx = (hg * W + wg) * T + tg_;
            float2 val;
            if (c < 9) {
                if (inb) {
                    float2 g = *(const float2*)(guidance + c * HWT + gidx);
                    val.x = g.x * ssig[c]; val.y = g.y * ssig[c];
                } else { val.x = 0.f; val.y = 0.f; }
            } else if (c < 12) {
                if (inb) val = *(const float2*)(estimands + (c - 9) * HWT + gidx);
                else     { val.x = -2.f; val.y = -2.f; }
            } else if (c < 15) {
                if (inb) val = *(const float2*)(variance + (c - 12) * HWT + gidx);
                else     { val.x = 0.f; val.y = 0.f; }
            } else {
                if (inb) val = *(const float2*)(images + (c - 15) * HWT + gidx);
                else     { val.x = 0.f; val.y = 0.f; }
            }
            int slot = (j + PHI2(x, y)) & 15;    // even -> 8B aligned
            *(float2*)(sm + c * PLANE + (y * HX + x) * HT + slot) = val;
        }
    }
    __syncthreads();

    // ---------------- per-thread decomposition ----------------
    const int og  = (tid >= 384) ? 1 : 0;
    const int lt  = tid - og * 384;
    const int tg  = lt >> 6;          // 0..5
    const int rr  = lt & 63;
    const int ty  = rr >> 3;
    const int tx  = rr & 7;
    const int tgb = tg * TT;          // even
    const int o0  = og ? 25 : 0;      // spatial-offset range [o0, o1)
    const int o1  = og ? 49 : 25;

    // center values held in registers
    float gc[9][TT], ec[3][TT], vc[3][TT], Pc[TT];
    {
        int yc = ty + 3, xc = tx + 3;
        int ph = PHI2(xc, yc);
        int rowoff = (yc * HX + xc) * HT;
        #pragma unroll
        for (int tt = 0; tt < TT; ++tt) {
            int sl = rowoff + ((tgb + tt + 2 + ph) & 15);
            float p = 0.0f;
            #pragma unroll
            for (int c = 0; c < 9; ++c) {
                float a = sm[c * PLANE + sl];
                gc[c][tt] = a;
                p = fmaf(a, a, p);           // same chain order as P_j below
            }
            Pc[tt] = p;
            #pragma unroll
            for (int c = 0; c < 3; ++c) ec[c][tt] = sm[(9 + c) * PLANE + sl];
            #pragma unroll
            for (int c = 0; c < 3; ++c) vc[c][tt] = sm[(12 + c) * PLANE + sl];
        }
    }

    float num0[TT], num1[TT], num2[TT], den[TT];
    #pragma unroll
    for (int tt = 0; tt < TT; ++tt) { num0[tt] = 0.f; num1[tt] = 0.f; num2[tt] = 0.f; den[tt] = 0.f; }

    // ---------------- main loop over this group's spatial offsets --------
    int dy = o0 / 7, dx = o0 - 7 * (o0 / 7);
    #pragma unroll 1
    for (int o = o0; o < o1; ++o) {
        int y = ty + dy;
        int x = tx + dx;
        int rowoff = (y * HX + x) * HT;
        int ph = PHI2(x, y);
        // three even pair bases, contiguous 8B each (wrap never splits a pair)
        int p0 = rowoff + ((tgb + 0 + ph) & 15);
        int p1 = rowoff + ((tgb + 2 + ph) & 15);
        int p2 = rowoff + ((tgb + 4 + ph) & 15);

        // guidance: dot products + on-the-fly neighbor norms
        float Pn[NL];
        float dot[TT][5];
        #pragma unroll
        for (int jj = 0; jj < NL; ++jj) Pn[jj] = 0.f;
        #pragma unroll
        for (int tt = 0; tt < TT; ++tt)
            #pragma unroll
            for (int dt = 0; dt < 5; ++dt) dot[tt][dt] = 0.f;

        #pragma unroll
        for (int c = 0; c < 9; ++c) {
            const float* sc = sm + c * PLANE;
            float2 r0 = *(const float2*)(sc + p0);
            float2 r1 = *(const float2*)(sc + p1);
            float2 r2 = *(const float2*)(sc + p2);
            float row[NL] = { r0.x, r0.y, r1.x, r1.y, r2.x, r2.y };
            #pragma unroll
            for (int jj = 0; jj < NL; ++jj) Pn[jj] = fmaf(row[jj], row[jj], Pn[jj]);
            #pragma unroll
            for (int tt = 0; tt < TT; ++tt)
                #pragma unroll
                for (int dt = 0; dt < 5; ++dt)
                    dot[tt][dt] = fmaf(row[tt + dt], gc[c][tt], dot[tt][dt]);
        }

        // load z-test operands (all channels) and image lanes
        float er[3][NL], vr[3][NL];
        #pragma unroll
        for (int c = 0; c < 3; ++c) {
            const float* se = sm + (9 + c)  * PLANE;
            const float* sv = sm + (12 + c) * PLANE;
            float2 e0 = *(const float2*)(se + p0);
            float2 e1 = *(const float2*)(se + p1);
            float2 e2 = *(const float2*)(se + p2);
            float2 v0 = *(const float2*)(sv + p0);
            float2 v1 = *(const float2*)(sv + p1);
            float2 v2 = *(const float2*)(sv + p2);
            er[c][0]=e0.x; er[c][1]=e0.y; er[c][2]=e1.x; er[c][3]=e1.y; er[c][4]=e2.x; er[c][5]=e2.y;
            vr[c][0]=v0.x; vr[c][1]=v0.y; vr[c][2]=v1.x; vr[c][3]=v1.y; vr[c][4]=v2.x; vr[c][5]=v2.y;
        }
        float i0[NL], i1[NL], i2[NL];
        {
            const float* s0 = sm + 15 * PLANE;
            const float* s1 = sm + 16 * PLANE;
            const float* s2 = sm + 17 * PLANE;
            float2 a0 = *(const float2*)(s0 + p0);
            float2 a1 = *(const float2*)(s0 + p1);
            float2 a2 = *(const float2*)(s0 + p2);
            i0[0]=a0.x; i0[1]=a0.y; i0[2]=a1.x; i0[3]=a1.y; i0[4]=a2.x; i0[5]=a2.y;
            float2 b0 = *(const float2*)(s1 + p0);
            float2 b1 = *(const float2*)(s1 + p1);
            float2 b2 = *(const float2*)(s1 + p2);
            i1[0]=b0.x; i1[1]=b0.y; i1[2]=b1.x; i1[3]=b1.y; i1[4]=b2.x; i1[5]=b2.y;
            float2 c0 = *(const float2*)(s2 + p0);
            float2 c1 = *(const float2*)(s2 + p1);
            float2 c2 = *(const float2*)(s2 + p2);
            i2[0]=c0.x; i2[1]=c0.y; i2[2]=c1.x; i2[3]=c1.y; i2[4]=c2.x; i2[5]=c2.y;
        }

        // per-pair: fused z-test (predicate OR chain, EXACT reference
        // rounding on each operand) + weight + accumulation
        #pragma unroll
        for (int tt = 0; tt < TT; ++tt) {
            #pragma unroll
            for (int dt = 0; dt < 5; ++dt) {
                const int l = tt + dt;
                // fail iff (d*d)*spp > T2*(vn+vc) for ANY channel; each
                // l_c / r_c uses the identical rn op sequence as reference.
                float d0 = __fsub_rn(er[0][l], ec[0][tt]);
                float l0v = __fmul_rn(__fmul_rn(d0, d0), sppf);
                float r0v = __fmul_rn(T2f, __fadd_rn(vr[0][l], vc[0][tt]));
                float d1 = __fsub_rn(er[1][l], ec[1][tt]);
                float l1v = __fmul_rn(__fmul_rn(d1, d1), sppf);
                float r1v = __fmul_rn(T2f, __fadd_rn(vr[1][l], vc[1][tt]));
                float d2 = __fsub_rn(er[2][l], ec[2][tt]);
                float l2v = __fmul_rn(__fmul_rn(d2, d2), sppf);
                float r2v = __fmul_rn(T2f, __fadd_rn(vr[2][l], vc[2][tt]));
                int f = (l0v > r0v) | (l1v > r1v) | (l2v > r2v);

                // exp2 argument: 2*dot - Pn - Pc
                float psum = Pn[l] + Pc[tt];
                float e = fmaf(2.0f, dot[tt][dt], -psum);
                e = f ? -350.0f : e;
                float wgt;
                asm("ex2.approx.f32 %0, %1;" : "=f"(wgt) : "f"(e));
                den[tt]  += wgt;
                num0[tt] = fmaf(wgt, i0[l], num0[tt]);
                num1[tt] = fmaf(wgt, i1[l], num1[tt]);
                num2[tt] = fmaf(wgt, i2[l], num2[tt]);
            }
        }

        if (++dx == 7) { dx = 0; ++dy; }
    }

    // ---------------- cross-group reduction through smem -----------------
    __syncthreads();   // everyone done reading the tile
    if (og) {
        int p = lt * 9;                 // stride 9: conflict-light
        sm[p + 0] = num0[0]; sm[p + 1] = num0[1];
        sm[p + 2] = num1[0]; sm[p + 3] = num1[1];
        sm[p + 4] = num2[0]; sm[p + 5] = num2[1];
        sm[p + 6] = den[0];  sm[p + 7] = den[1];
    }
    __syncthreads();

    // ---------------- write out (group A only) ----------------
    if (!og) {
        int p = lt * 9;
        num0[0] += sm[p + 0]; num0[1] += sm[p + 1];
        num1[0] += sm[p + 2]; num1[1] += sm[p + 3];
        num2[0] += sm[p + 4]; num2[1] += sm[p + 5];
        den[0]  += sm[p + 6]; den[1]  += sm[p + 7];

        const int hh = h0 + ty;
        const int ww = w0 + tx;
        #pragma unroll
        for (int tt = 0; tt < TT; ++tt) {
            int t = t0 + tgb + tt;
            float inv = 1.0f / den[tt];
            int base = (hh * W + ww) * T + t;
            out[base]            = num0[tt] * inv;
            out[HWT + base]      = num1[tt] * inv;
            out[2 * HWT + base]  = num2[tt] * inv;
        }
    }
}

extern "C" void kernel_launch(void* const* d_in, const int* in_sizes, int n_in,
                              void* d_out, int out_size)
{
    const float* images   = (const float*)d_in[0];
    const float* guidance = (const float*)d_in[1];
    const float* estim    = (const float*)d_in[2];
    const float* var      = (const float*)d_in[3];
    const float* sig      = (const float*)d_in[4];
    const int*   spp      = (const int*)d_in[5];
    float* out = (float*)d_out;

    cudaFuncSetAttribute(denoise_kernel,
                         cudaFuncAttributeMaxDynamicSharedMemorySize,
                         SMEM_FLOATS * (int)sizeof(float));

    dim3 grid(W / OW, H / OH, T / OT);   // 32 x 32 x 4
    denoise_kernel<<<grid, NTHREADS, SMEM_FLOATS * sizeof(float)>>>(
        images, guidance, estim, var, sig, spp, out);
}